// round 15
// baseline (speedup 1.0000x reference)
#include <cuda_runtime.h>
#include <cuda_fp16.h>
#include <cstdint>

// Problem shape (fixed by the dataset)
#define NB_ 8
#define T_  200
#define U_  50
#define J_  512
#define V_  500
#define NT_ (NB_*T_)   // 1600
#define NU_ (NB_*U_)   // 400
// rows of the big GEMM: NT_*U_ = 80000 = 625 * 128

// Scratch
__device__ float g_encP[NT_*J_];     // [1600][512] projected enc (+bias)
__device__ float g_decP[NU_*J_];     // [400][512]  projected dec (+bias)
// W_out pre-packed to fp16 fragment order:
//   [globalNa(64)][ks(32)][lane(32)] uint2   (globalNa = v/8)
__device__ __align__(16) uint2 g_Bh[64*32*32];       // 512 KB
// Activations tanh(encP+decP) pre-packed to fp16 A-fragment order:
//   [mtile(625)][matom(8)][ks(32)][lane(32)] uint4
__device__ __align__(16) uint4 g_Ah[625*8*32*32];    // 82 MB

__device__ __forceinline__ uint32_t smem_u32(const void* p) {
    uint32_t a;
    asm("{ .reg .u64 t; cvta.to.shared.u64 t, %1; cvt.u32.u64 %0, t; }"
        : "=r"(a) : "l"(p));
    return a;
}
__device__ __forceinline__ float atanh_(float x) {
    float y;
    asm("tanh.approx.f32 %0, %1;" : "=f"(y) : "f"(x));
    return y;
}
__device__ __forceinline__ uint32_t h2u(float lo, float hi) {
    __half2 h = __floats2half2_rn(lo, hi);
    return *(uint32_t*)&h;
}
// split a float pair into fp16 hi + fp16 residual lo (packed half2 words)
__device__ __forceinline__ void split2(float a, float b, uint32_t& hi, uint32_t& lo) {
    __half ha = __float2half_rn(a), hb = __float2half_rn(b);
    float ra = a - __half2float(ha), rb = b - __half2float(hb);
    __half2 h = __halves2half2(ha, hb);
    __half2 l = __floats2half2_rn(ra, rb);
    hi = *(uint32_t*)&h;
    lo = *(uint32_t*)&l;
}

#define HMMA16816(ac, a0,a1,a2,a3, b0,b1)                                      \
    asm volatile(                                                              \
        "mma.sync.aligned.m16n8k16.row.col.f32.f16.f16.f32 "                   \
        "{%0,%1,%2,%3}, {%4,%5,%6,%7}, {%8,%9}, {%0,%1,%2,%3};"                \
        : "+f"((ac)[0]), "+f"((ac)[1]), "+f"((ac)[2]), "+f"((ac)[3])           \
        : "r"(a0), "r"(a1), "r"(a2), "r"(a3), "r"(b0), "r"(b1))

// ---------------------------------------------------------------------------
// W_out -> fp16 fragment-packed gmem
// ---------------------------------------------------------------------------
__global__ __launch_bounds__(256) void pack_w(const float* __restrict__ W)
{
    const int idx  = blockIdx.x * 256 + threadIdx.x;   // 65536 total
    const int lane = idx & 31;
    const int ks   = (idx >> 5) & 31;
    const int gna  = idx >> 10;                         // 0..63
    const int g = lane >> 2, t = lane & 3;
    const int v = gna * 8 + g;
    const int k = ks * 16 + 2 * t;
    float w0 = 0.f, w1 = 0.f, w2 = 0.f, w3 = 0.f;
    if (v < V_) {
        const float* r = W + (size_t)v * J_;
        w0 = r[k]; w1 = r[k+1]; w2 = r[k+8]; w3 = r[k+9];
    }
    uint2 o;
    o.x = h2u(w0, w1);
    o.y = h2u(w2, w3);
    g_Bh[idx] = o;
}

// ---------------------------------------------------------------------------
// Activation kernel: act = fp16(tanh(encP+decP)), written in fragment order.
// ---------------------------------------------------------------------------
__global__ __launch_bounds__(256) void act_kernel()
{
    const int idx  = blockIdx.x * 256 + threadIdx.x;   // 5,120,000
    const int lane = idx & 31;
    const int ks   = (idx >> 5) & 31;
    const int ma   = (idx >> 10) & 7;
    const int mt   = idx >> 13;                        // 0..624
    const int g = lane >> 2, t = lane & 3;

    const int row0 = mt * 128 + ma * 16 + g;
    const int row1 = row0 + 8;
    const int nt0 = row0 / U_;
    const int u0  = row0 - nt0 * U_;
    const int nt1 = row1 / U_;
    const int u1  = row1 - nt1 * U_;
    const float* encR0 = g_encP + (size_t)nt0 * J_;
    const float* decR0 = g_decP + ((size_t)(nt0 / T_) * U_ + u0) * J_;
    const float* encR1 = g_encP + (size_t)nt1 * J_;
    const float* decR1 = g_decP + ((size_t)(nt1 / T_) * U_ + u1) * J_;

    const int kb = ks * 16 + 2 * t;
    float2 e0a = *(const float2*)(encR0 + kb);
    float2 d0a = *(const float2*)(decR0 + kb);
    float2 e0b = *(const float2*)(encR0 + kb + 8);
    float2 d0b = *(const float2*)(decR0 + kb + 8);
    float2 e1a = *(const float2*)(encR1 + kb);
    float2 d1a = *(const float2*)(decR1 + kb);
    float2 e1b = *(const float2*)(encR1 + kb + 8);
    float2 d1b = *(const float2*)(decR1 + kb + 8);

    uint4 o;
    o.x = h2u(atanh_(e0a.x + d0a.x), atanh_(e0a.y + d0a.y));
    o.y = h2u(atanh_(e1a.x + d1a.x), atanh_(e1a.y + d1a.y));
    o.z = h2u(atanh_(e0b.x + d0b.x), atanh_(e0b.y + d0b.y));
    o.w = h2u(atanh_(e1b.x + d1b.x), atanh_(e1b.y + d1b.y));
    g_Ah[idx] = o;
}

// ---------------------------------------------------------------------------
// Projection GEMM via split-fp16 HMMA (hi+lo, drop lo*lo; err ~2^-21):
//   C[m][j] = sum_k A[m][k] W[j][k] + bias[j],  K = 512
// CTA tile 64 rows x 64 cols; grid (8 jtiles, 32 mtiles: 25 enc + 7 dec).
// ---------------------------------------------------------------------------
__global__ __launch_bounds__(256) void proj_hmma(
    const float* __restrict__ enc, const float* __restrict__ Wenc,
    const float* __restrict__ benc, float* __restrict__ encP,
    const float* __restrict__ dec, const float* __restrict__ Wdec,
    const float* __restrict__ bdec, float* __restrict__ decP)
{
    __shared__ __align__(16) uint32_t Ah_s[1024], Al_s[1024];   // 4KB each
    __shared__ __align__(16) uint32_t Bh_s[1024], Bl_s[1024];   // 4KB each

    const float *A, *W, *bias; float* C; int M, m0;
    if (blockIdx.y < 25) { A = enc; W = Wenc; bias = benc; C = encP; M = NT_; m0 = blockIdx.y * 64; }
    else                 { A = dec; W = Wdec; bias = bdec; C = decP; M = NU_; m0 = (blockIdx.y - 25) * 64; }

    const int tid  = threadIdx.x;
    const int wid  = tid >> 5;
    const int lane = tid & 31;
    const int j0   = blockIdx.x * 64;
    const int warpM = wid & 3;
    const int warpN = wid >> 2;

    const int sa_m = (tid >> 5) & 3;
    const int sa_t = tid & 3;
    const int sa_lane = tid & 31;
    const int rowA0 = m0 + sa_m * 16 + ((tid >> 2) & 7);
    const int rowA1 = rowA0 + 8;
    const int ts    = tid & 127;
    const int sb_na = ts >> 4;
    const int sb_ksl = (ts >> 3) & 1;
    const int sb_lq = ts & 7;
    const int jW = j0 + sb_na * 8 + sb_lq;

    float acc[4][4];
#pragma unroll
    for (int j = 0; j < 4; j++)
#pragma unroll
        for (int c = 0; c < 4; c++) acc[j][c] = 0.f;

#pragma unroll 1
    for (int kc = 0; kc < 16; kc++) {
        const int k0 = kc * 32;
        if (tid < 128) {
            const float* r0p = A + (size_t)rowA0 * 512;
            const float* r1p = A + (size_t)rowA1 * 512;
            const bool ok0 = rowA0 < M, ok1 = rowA1 < M;
#pragma unroll
            for (int ksl = 0; ksl < 2; ksl++) {
                const int kb = k0 + ksl * 16 + 2 * sa_t;
                float2 z = make_float2(0.f, 0.f);
                float2 x0a = ok0 ? *(const float2*)(r0p + kb)     : z;
                float2 x0b = ok0 ? *(const float2*)(r0p + kb + 8) : z;
                float2 x1a = ok1 ? *(const float2*)(r1p + kb)     : z;
                float2 x1b = ok1 ? *(const float2*)(r1p + kb + 8) : z;
                uint4 hi, lo;
                split2(x0a.x, x0a.y, hi.x, lo.x);
                split2(x1a.x, x1a.y, hi.y, lo.y);
                split2(x0b.x, x0b.y, hi.z, lo.z);
                split2(x1b.x, x1b.y, hi.w, lo.w);
                const int idx = ((sa_m * 2 + ksl) * 32 + sa_lane) * 4;
                *(uint4*)&Ah_s[idx] = hi;
                *(uint4*)&Al_s[idx] = lo;
            }
        } else {
            const float* wr = W + (size_t)jW * 512;
            const int kb = k0 + sb_ksl * 16;
            float wv[16];
            *(float4*)&wv[0]  = *(const float4*)(wr + kb);
            *(float4*)&wv[4]  = *(const float4*)(wr + kb + 4);
            *(float4*)&wv[8]  = *(const float4*)(wr + kb + 8);
            *(float4*)&wv[12] = *(const float4*)(wr + kb + 12);
#pragma unroll
            for (int t = 0; t < 4; t++) {
                const int l = sb_lq * 4 + t;
                uint32_t hx, lx, hy, ly;
                split2(wv[2*t],     wv[2*t + 1], hx, lx);
                split2(wv[2*t + 8], wv[2*t + 9], hy, ly);
                const int idx = ((sb_na * 2 + sb_ksl) * 32 + l) * 2;
                Bh_s[idx] = hx; Bh_s[idx + 1] = hy;
                Bl_s[idx] = lx; Bl_s[idx + 1] = ly;
            }
        }
        __syncthreads();

#pragma unroll
        for (int ksl = 0; ksl < 2; ksl++) {
            const int aidx = ((warpM * 2 + ksl) * 32 + lane) * 4;
            const uint4 ah = *(const uint4*)&Ah_s[aidx];
            const uint4 al = *(const uint4*)&Al_s[aidx];
#pragma unroll
            for (int j = 0; j < 4; j++) {
                const int bidx = (((warpN * 4 + j) * 2 + ksl) * 32 + lane) * 2;
                const uint2 bh = *(const uint2*)&Bh_s[bidx];
                const uint2 bl = *(const uint2*)&Bl_s[bidx];
                HMMA16816(acc[j], ah.x, ah.y, ah.z, ah.w, bh.x, bh.y);
                HMMA16816(acc[j], ah.x, ah.y, ah.z, ah.w, bl.x, bl.y);
                HMMA16816(acc[j], al.x, al.y, al.z, al.w, bh.x, bh.y);
            }
        }
        __syncthreads();
    }

    const int rsub = lane >> 2;
    const int cp   = (lane & 3) * 2;
#pragma unroll
    for (int j = 0; j < 4; j++) {
        const int col = j0 + (warpN * 4 + j) * 8 + cp;
        const float2 bb = *(const float2*)(bias + col);
        const int m0r = m0 + warpM * 16 + rsub;
        if (m0r < M) {
            float2 o; o.x = acc[j][0] + bb.x; o.y = acc[j][1] + bb.y;
            *(float2*)(C + (size_t)m0r * 512 + col) = o;
        }
        if (m0r + 8 < M) {
            float2 o; o.x = acc[j][2] + bb.x; o.y = acc[j][3] + bb.y;
            *(float2*)(C + (size_t)(m0r + 8) * 512 + col) = o;
        }
    }
}

// ---------------------------------------------------------------------------
// Main kernel: pure fp16 GEMM, 128x128 CTA tile, 128 threads (4 warps),
// warp tile 64x64 (4 matoms x 8 natoms) -> smem reads 4B/HMMA-lane (was 6B).
// grid (4, 625), 2 CTAs/SM. acc = 4x8x4 = 128 regs. BK=32 (2 ksteps).
// Smem: 3 stages x (A 8KB + B 8KB) = 48KB static per CTA.
// ---------------------------------------------------------------------------
__global__ __launch_bounds__(128, 2) void joiner_hmma(
    const float* __restrict__ bout,   // [500]
    float* __restrict__ out)          // [80000][500]
{
    __shared__ __align__(16) uint32_t smem[3 * 4096];   // 48 KB

    const int tid  = threadIdx.x;      // 0..127
    const int wid  = tid >> 5;         // 0..3
    const int lane = tid & 31;
    const int mt   = blockIdx.y;               // 0..624
    const long r0  = (long)mt * 128;
    const int vt   = blockIdx.x;               // 0..3
    const int v0   = vt * 128;
    const int warpM = wid & 1;    // 64-row half
    const int warpN = wid >> 1;   // 64-col half

    const uint32_t smemBase = smem_u32(smem);
    const char* ah_base = (const char*)g_Ah + (long)mt * (8 * 32 * 32 * 16);
    const char* bh_base = (const char*)g_Bh;

    // copy duties: 4 A-slots + 4 B-slots of 16B per thread per chunk
    auto copyAB = [&](int kc, int st) {
        const uint32_t sb = smemBase + (uint32_t)st * 16384u;
#pragma unroll
        for (int q = 0; q < 4; q++) {
            const int s = tid * 4 + q;                  // 0..511
            // A slot: [ma(8)][ksl(2)][lane(32)] x 16B
            const int ama = s >> 6, aksl = (s >> 5) & 1, alane = s & 31;
            const long  ga = (long)((ama * 32 + 2 * kc + aksl) * 32 + alane) * 16;
            const uint32_t oa = sb + (uint32_t)(((ama * 2 + aksl) * 32 + alane) * 16);
            asm volatile("cp.async.cg.shared.global [%0], [%1], 16;"
                         :: "r"(oa), "l"(ah_base + ga));
            // B slot: [na(16)][ksl(2)][lp(16)] x 16B
            const int bna = s >> 5, bksl = (s >> 4) & 1, blp = s & 15;
            const int gna = vt * 16 + bna;
            const long  gb = (long)((gna * 32 + 2 * kc + bksl) * 256 + blp * 16);
            const uint32_t ob = sb + 8192u
                                + (uint32_t)((bna * 2 + bksl) * 256 + blp * 16);
            asm volatile("cp.async.cg.shared.global [%0], [%1], 16;"
                         :: "r"(ob), "l"(bh_base + gb));
        }
        asm volatile("cp.async.commit_group;" ::: "memory");
    };

    float acc[4][8][4];
#pragma unroll
    for (int i = 0; i < 4; i++)
#pragma unroll
        for (int j = 0; j < 8; j++)
#pragma unroll
            for (int c = 0; c < 4; c++) acc[i][j][c] = 0.f;

    // prologue: prefetch chunks 0 and 1
    copyAB(0, 0);
    copyAB(1, 1);

#pragma unroll 1
    for (int kc = 0; kc < 16; kc++) {
        if (kc < 14)
            asm volatile("cp.async.wait_group 1;" ::: "memory");
        else
            asm volatile("cp.async.wait_group 0;" ::: "memory");
        __syncthreads();

        if (kc < 14) copyAB(kc + 2, (kc + 2) % 3);

        const uint32_t* Ab = smem + (kc % 3) * 4096;
        const uint32_t* Bb = Ab + 2048;
#pragma unroll
        for (int ksl = 0; ksl < 2; ksl++) {
            uint32_t af[4][4];
            uint32_t bf[8][2];
#pragma unroll
            for (int mi = 0; mi < 4; mi++) {
                const uint4 va = *(const uint4*)
                    (Ab + (((warpM * 4 + mi) * 2 + ksl) * 32 + lane) * 4);
                af[mi][0] = va.x; af[mi][1] = va.y; af[mi][2] = va.z; af[mi][3] = va.w;
            }
#pragma unroll
            for (int j = 0; j < 8; j++) {
                const uint2 vb = *(const uint2*)
                    (Bb + (((warpN * 8 + j) * 2 + ksl) * 32 + lane) * 2);
                bf[j][0] = vb.x; bf[j][1] = vb.y;
            }
#pragma unroll
            for (int mi = 0; mi < 4; mi++)
#pragma unroll
                for (int j = 0; j < 8; j++)
                    HMMA16816(acc[mi][j], af[mi][0], af[mi][1], af[mi][2], af[mi][3],
                              bf[j][0], bf[j][1]);
        }
    }

    // epilogue: registers -> gmem, +bias, float2 stores
    const int cpair = (lane & 3) * 2;
    const int rsub  = lane >> 2;
#pragma unroll
    for (int j = 0; j < 8; j++) {
        const int col = v0 + warpN * 64 + j * 8 + cpair;
        if (col >= V_) continue;                  // V_ even: pair never straddles
        const float2 bb = *(const float2*)(bout + col);
#pragma unroll
        for (int mi = 0; mi < 4; mi++) {
            const long rr = r0 + warpM * 64 + mi * 16 + rsub;
            float2 o0, o1;
            o0.x = acc[mi][j][0] + bb.x;
            o0.y = acc[mi][j][1] + bb.y;
            o1.x = acc[mi][j][2] + bb.x;
            o1.y = acc[mi][j][3] + bb.y;
            *(float2*)(out + rr * (long)V_ + col)       = o0;
            *(float2*)(out + (rr + 8) * (long)V_ + col) = o1;
        }
    }
}

// ---------------------------------------------------------------------------
extern "C" void kernel_launch(void* const* d_in, const int* in_sizes, int n_in,
                              void* d_out, int out_size)
{
    (void)in_sizes; (void)n_in; (void)out_size;
    const float* encoder_out = (const float*)d_in[0];  // [8,200,512]
    const float* decoder_out = (const float*)d_in[1];  // [8,50,512]
    const float* W_enc       = (const float*)d_in[2];  // [512,512]
    const float* b_enc       = (const float*)d_in[3];  // [512]
    const float* W_dec       = (const float*)d_in[4];  // [512,512]
    const float* b_dec       = (const float*)d_in[5];  // [512]
    const float* W_out       = (const float*)d_in[6];  // [500,512]
    const float* b_out       = (const float*)d_in[7];  // [500]
    float* out = (float*)d_out;                        // [8,200,50,500]

    float* encP = nullptr;
    float* decP = nullptr;
    cudaGetSymbolAddress((void**)&encP, g_encP);
    cudaGetSymbolAddress((void**)&decP, g_decP);

    // pack W_out to fp16 fragment order (independent of projections)
    pack_w<<<256, 256>>>(W_out);

    // projections via split-fp16 HMMA (enc: 25 mtiles, dec: 7 mtiles)
    {
        dim3 grid(8, 32);
        proj_hmma<<<grid, 256>>>(encoder_out, W_enc, b_enc, encP,
                                 decoder_out, W_dec, b_dec, decP);
    }
    // activations: tanh(encP+decP) -> fp16 fragment-packed gmem
    act_kernel<<<20000, 256>>>();

    // main pure fp16 GEMM (128x128 tiles, 64x64 warp tiles, 2 CTAs/SM)
    {
        dim3 grid(4, 625);   // N-tiles x M-tiles
        joiner_hmma<<<grid, 128>>>(b_out, out);
    }
}

// round 16
// speedup vs baseline: 1.0171x; 1.0171x over previous
#include <cuda_runtime.h>
#include <cuda_fp16.h>
#include <cstdint>

// Problem shape (fixed by the dataset)
#define NB_ 8
#define T_  200
#define U_  50
#define J_  512
#define V_  500
#define NT_ (NB_*T_)   // 1600
#define NU_ (NB_*U_)   // 400
// rows of the big GEMM: NT_*U_ = 80000 = 625 * 128

// Scratch
__device__ float g_encP[NT_*J_];     // [1600][512] projected enc (+bias)
__device__ float g_decP[NU_*J_];     // [400][512]  projected dec (+bias)
// W_out pre-packed fp16, PAIRED fragment order:
//   [gpair(32)][ks(32)][lane(32)] uint4
//   pair p covers natoms {2p, 2p+1}; lane: g=lane>>2, t=lane&3
//   .x={W[16p+g][k+2t..]} .y={W[16p+g][k+2t+8..]}
//   .z={W[16p+8+g][k+2t..]} .w={W[16p+8+g][k+2t+8..]}   (k = ks*16)
__device__ __align__(16) uint4 g_Bh[32*32*32];       // 512 KB
// Activations tanh(encP+decP) pre-packed to fp16 A-fragment order:
//   [mtile(625)][matom(8)][ks(32)][lane(32)] uint4
__device__ __align__(16) uint4 g_Ah[625*8*32*32];    // 82 MB

__device__ __forceinline__ uint32_t smem_u32(const void* p) {
    uint32_t a;
    asm("{ .reg .u64 t; cvta.to.shared.u64 t, %1; cvt.u32.u64 %0, t; }"
        : "=r"(a) : "l"(p));
    return a;
}
__device__ __forceinline__ float atanh_(float x) {
    float y;
    asm("tanh.approx.f32 %0, %1;" : "=f"(y) : "f"(x));
    return y;
}
__device__ __forceinline__ uint32_t h2u(float lo, float hi) {
    __half2 h = __floats2half2_rn(lo, hi);
    return *(uint32_t*)&h;
}
// split a float pair into fp16 hi + fp16 residual lo (packed half2 words)
__device__ __forceinline__ void split2(float a, float b, uint32_t& hi, uint32_t& lo) {
    __half ha = __float2half_rn(a), hb = __float2half_rn(b);
    float ra = a - __half2float(ha), rb = b - __half2float(hb);
    __half2 h = __halves2half2(ha, hb);
    __half2 l = __floats2half2_rn(ra, rb);
    hi = *(uint32_t*)&h;
    lo = *(uint32_t*)&l;
}

#define HMMA16816(ac, a0,a1,a2,a3, b0,b1)                                      \
    asm volatile(                                                              \
        "mma.sync.aligned.m16n8k16.row.col.f32.f16.f16.f32 "                   \
        "{%0,%1,%2,%3}, {%4,%5,%6,%7}, {%8,%9}, {%0,%1,%2,%3};"                \
        : "+f"((ac)[0]), "+f"((ac)[1]), "+f"((ac)[2]), "+f"((ac)[3])           \
        : "r"(a0), "r"(a1), "r"(a2), "r"(a3), "r"(b0), "r"(b1))

// ---------------------------------------------------------------------------
// W_out -> paired fp16 fragment order
// ---------------------------------------------------------------------------
__global__ __launch_bounds__(256) void pack_w(const float* __restrict__ W)
{
    const int idx  = blockIdx.x * 256 + threadIdx.x;   // 32768 total
    const int lane = idx & 31;
    const int ks   = (idx >> 5) & 31;
    const int gp   = idx >> 10;                         // 0..31
    const int g = lane >> 2, t = lane & 3;
    const int v0 = gp * 16 + g;          // natom 2p
    const int v1 = v0 + 8;               // natom 2p+1
    const int k = ks * 16 + 2 * t;
    float a0=0.f,a1=0.f,a2=0.f,a3=0.f, b0=0.f,b1=0.f,b2=0.f,b3=0.f;
    if (v0 < V_) {
        const float* r = W + (size_t)v0 * J_;
        a0 = r[k]; a1 = r[k+1]; a2 = r[k+8]; a3 = r[k+9];
    }
    if (v1 < V_) {
        const float* r = W + (size_t)v1 * J_;
        b0 = r[k]; b1 = r[k+1]; b2 = r[k+8]; b3 = r[k+9];
    }
    uint4 o;
    o.x = h2u(a0, a1);
    o.y = h2u(a2, a3);
    o.z = h2u(b0, b1);
    o.w = h2u(b2, b3);
    g_Bh[idx] = o;
}

// ---------------------------------------------------------------------------
// Activation kernel: act = fp16(tanh(encP+decP)), fragment order.
// ---------------------------------------------------------------------------
__global__ __launch_bounds__(256) void act_kernel()
{
    const int idx  = blockIdx.x * 256 + threadIdx.x;   // 5,120,000
    const int lane = idx & 31;
    const int ks   = (idx >> 5) & 31;
    const int ma   = (idx >> 10) & 7;
    const int mt   = idx >> 13;                        // 0..624
    const int g = lane >> 2, t = lane & 3;

    const int row0 = mt * 128 + ma * 16 + g;
    const int row1 = row0 + 8;
    const int nt0 = row0 / U_;
    const int u0  = row0 - nt0 * U_;
    const int nt1 = row1 / U_;
    const int u1  = row1 - nt1 * U_;
    const float* encR0 = g_encP + (size_t)nt0 * J_;
    const float* decR0 = g_decP + ((size_t)(nt0 / T_) * U_ + u0) * J_;
    const float* encR1 = g_encP + (size_t)nt1 * J_;
    const float* decR1 = g_decP + ((size_t)(nt1 / T_) * U_ + u1) * J_;

    const int kb = ks * 16 + 2 * t;
    float2 e0a = *(const float2*)(encR0 + kb);
    float2 d0a = *(const float2*)(decR0 + kb);
    float2 e0b = *(const float2*)(encR0 + kb + 8);
    float2 d0b = *(const float2*)(decR0 + kb + 8);
    float2 e1a = *(const float2*)(encR1 + kb);
    float2 d1a = *(const float2*)(decR1 + kb);
    float2 e1b = *(const float2*)(encR1 + kb + 8);
    float2 d1b = *(const float2*)(decR1 + kb + 8);

    uint4 o;
    o.x = h2u(atanh_(e0a.x + d0a.x), atanh_(e0a.y + d0a.y));
    o.y = h2u(atanh_(e1a.x + d1a.x), atanh_(e1a.y + d1a.y));
    o.z = h2u(atanh_(e0b.x + d0b.x), atanh_(e0b.y + d0b.y));
    o.w = h2u(atanh_(e1b.x + d1b.x), atanh_(e1b.y + d1b.y));
    g_Ah[idx] = o;
}

// ---------------------------------------------------------------------------
// Projection GEMM via split-fp16 HMMA (hi+lo, drop lo*lo; err ~2^-21):
//   C[m][j] = sum_k A[m][k] W[j][k] + bias[j],  K = 512
// CTA tile 64 rows x 64 cols; grid (8 jtiles, 32 mtiles: 25 enc + 7 dec).
// ---------------------------------------------------------------------------
__global__ __launch_bounds__(256) void proj_hmma(
    const float* __restrict__ enc, const float* __restrict__ Wenc,
    const float* __restrict__ benc, float* __restrict__ encP,
    const float* __restrict__ dec, const float* __restrict__ Wdec,
    const float* __restrict__ bdec, float* __restrict__ decP)
{
    __shared__ __align__(16) uint32_t Ah_s[1024], Al_s[1024];   // 4KB each
    __shared__ __align__(16) uint32_t Bh_s[1024], Bl_s[1024];   // 4KB each

    const float *A, *W, *bias; float* C; int M, m0;
    if (blockIdx.y < 25) { A = enc; W = Wenc; bias = benc; C = encP; M = NT_; m0 = blockIdx.y * 64; }
    else                 { A = dec; W = Wdec; bias = bdec; C = decP; M = NU_; m0 = (blockIdx.y - 25) * 64; }

    const int tid  = threadIdx.x;
    const int wid  = tid >> 5;
    const int lane = tid & 31;
    const int j0   = blockIdx.x * 64;
    const int warpM = wid & 3;
    const int warpN = wid >> 2;

    const int sa_m = (tid >> 5) & 3;
    const int sa_t = tid & 3;
    const int sa_lane = tid & 31;
    const int rowA0 = m0 + sa_m * 16 + ((tid >> 2) & 7);
    const int rowA1 = rowA0 + 8;
    const int ts    = tid & 127;
    const int sb_na = ts >> 4;
    const int sb_ksl = (ts >> 3) & 1;
    const int sb_lq = ts & 7;
    const int jW = j0 + sb_na * 8 + sb_lq;

    float acc[4][4];
#pragma unroll
    for (int j = 0; j < 4; j++)
#pragma unroll
        for (int c = 0; c < 4; c++) acc[j][c] = 0.f;

#pragma unroll 1
    for (int kc = 0; kc < 16; kc++) {
        const int k0 = kc * 32;
        if (tid < 128) {
            const float* r0p = A + (size_t)rowA0 * 512;
            const float* r1p = A + (size_t)rowA1 * 512;
            const bool ok0 = rowA0 < M, ok1 = rowA1 < M;
#pragma unroll
            for (int ksl = 0; ksl < 2; ksl++) {
                const int kb = k0 + ksl * 16 + 2 * sa_t;
                float2 z = make_float2(0.f, 0.f);
                float2 x0a = ok0 ? *(const float2*)(r0p + kb)     : z;
                float2 x0b = ok0 ? *(const float2*)(r0p + kb + 8) : z;
                float2 x1a = ok1 ? *(const float2*)(r1p + kb)     : z;
                float2 x1b = ok1 ? *(const float2*)(r1p + kb + 8) : z;
                uint4 hi, lo;
                split2(x0a.x, x0a.y, hi.x, lo.x);
                split2(x1a.x, x1a.y, hi.y, lo.y);
                split2(x0b.x, x0b.y, hi.z, lo.z);
                split2(x1b.x, x1b.y, hi.w, lo.w);
                const int idx = ((sa_m * 2 + ksl) * 32 + sa_lane) * 4;
                *(uint4*)&Ah_s[idx] = hi;
                *(uint4*)&Al_s[idx] = lo;
            }
        } else {
            const float* wr = W + (size_t)jW * 512;
            const int kb = k0 + sb_ksl * 16;
            float wv[16];
            *(float4*)&wv[0]  = *(const float4*)(wr + kb);
            *(float4*)&wv[4]  = *(const float4*)(wr + kb + 4);
            *(float4*)&wv[8]  = *(const float4*)(wr + kb + 8);
            *(float4*)&wv[12] = *(const float4*)(wr + kb + 12);
#pragma unroll
            for (int t = 0; t < 4; t++) {
                const int l = sb_lq * 4 + t;
                uint32_t hx, lx, hy, ly;
                split2(wv[2*t],     wv[2*t + 1], hx, lx);
                split2(wv[2*t + 8], wv[2*t + 9], hy, ly);
                const int idx = ((sb_na * 2 + sb_ksl) * 32 + l) * 2;
                Bh_s[idx] = hx; Bh_s[idx + 1] = hy;
                Bl_s[idx] = lx; Bl_s[idx + 1] = ly;
            }
        }
        __syncthreads();

#pragma unroll
        for (int ksl = 0; ksl < 2; ksl++) {
            const int aidx = ((warpM * 2 + ksl) * 32 + lane) * 4;
            const uint4 ah = *(const uint4*)&Ah_s[aidx];
            const uint4 al = *(const uint4*)&Al_s[aidx];
#pragma unroll
            for (int j = 0; j < 4; j++) {
                const int bidx = (((warpN * 4 + j) * 2 + ksl) * 32 + lane) * 2;
                const uint2 bh = *(const uint2*)&Bh_s[bidx];
                const uint2 bl = *(const uint2*)&Bl_s[bidx];
                HMMA16816(acc[j], ah.x, ah.y, ah.z, ah.w, bh.x, bh.y);
                HMMA16816(acc[j], ah.x, ah.y, ah.z, ah.w, bl.x, bl.y);
                HMMA16816(acc[j], al.x, al.y, al.z, al.w, bh.x, bh.y);
            }
        }
        __syncthreads();
    }

    const int rsub = lane >> 2;
    const int cp   = (lane & 3) * 2;
#pragma unroll
    for (int j = 0; j < 4; j++) {
        const int col = j0 + (warpN * 4 + j) * 8 + cp;
        const float2 bb = *(const float2*)(bias + col);
        const int m0r = m0 + warpM * 16 + rsub;
        if (m0r < M) {
            float2 o; o.x = acc[j][0] + bb.x; o.y = acc[j][1] + bb.y;
            *(float2*)(C + (size_t)m0r * 512 + col) = o;
        }
        if (m0r + 8 < M) {
            float2 o; o.x = acc[j][2] + bb.x; o.y = acc[j][3] + bb.y;
            *(float2*)(C + (size_t)(m0r + 8) * 512 + col) = o;
        }
    }
}

// ---------------------------------------------------------------------------
// Main kernel: pure fp16 GEMM. 128x128 CTA tile, 256 threads (8 warps),
// warp tile 32x64 (R14 proven residency), BK=64 (4 ksteps) -> 8 chunks,
// half the barriers of R14. B LDS via paired uint4 (one LDS.128 = 2 natoms).
// grid (4, 625), 2 CTAs/SM. Smem: 3 stages x 32KB = 96KB dynamic.
// ---------------------------------------------------------------------------
#define SMEM_BYTES (3 * 32768)

__global__ __launch_bounds__(256, 2) void joiner_hmma(
    const float* __restrict__ bout,   // [500]
    float* __restrict__ out)          // [80000][500]
{
    extern __shared__ __align__(16) uint32_t smem[];

    const int tid  = threadIdx.x;
    const int wid  = tid >> 5;
    const int lane = tid & 31;
    const int mt   = blockIdx.y;               // 0..624
    const long r0  = (long)mt * 128;
    const int vt   = blockIdx.x;               // 0..3
    const int v0   = vt * 128;
    const int warpM = wid & 3;    // 32-row group (2 matoms)
    const int warpN = wid >> 2;   // 64-col group (8 natoms = 4 pairs)

    const uint32_t smemBase = smem_u32(smem);
    const char* ah_base = (const char*)g_Ah + (long)mt * (8 * 32 * 32 * 16);
    const char* bh_base = (const char*)g_Bh;

    // copy duties per chunk: A 1024 slots + B 1024 slots of 16B, 256 threads
    // -> 4 A-slots + 4 B-slots per thread.
    auto copyAB = [&](int kc, int st) {
        const uint32_t sb = smemBase + (uint32_t)st * 32768u;
#pragma unroll
        for (int q = 0; q < 4; q++) {
            const int s = tid * 4 + q;                  // 0..1023
            // A slot: [ma(8)][ksl(4)][lane(32)] x 16B
            const int ama = s >> 7, aksl = (s >> 5) & 3, alane = s & 31;
            const long  ga = (long)((ama * 32 + 4 * kc + aksl) * 32 + alane) * 16;
            const uint32_t oa = sb + (uint32_t)(((ama * 4 + aksl) * 32 + alane) * 16);
            asm volatile("cp.async.cg.shared.global [%0], [%1], 16;"
                         :: "r"(oa), "l"(ah_base + ga));
            // B slot: [pair(8)][ksl(4)][lane(32)] x 16B
            const int bp = s >> 7, bksl = (s >> 5) & 3, blane = s & 31;
            const long  gb = (long)(((vt * 8 + bp) * 32 + 4 * kc + bksl) * 32 + blane) * 16;
            const uint32_t ob = sb + 16384u
                                + (uint32_t)(((bp * 4 + bksl) * 32 + blane) * 16);
            asm volatile("cp.async.cg.shared.global [%0], [%1], 16;"
                         :: "r"(ob), "l"(bh_base + gb));
        }
        asm volatile("cp.async.commit_group;" ::: "memory");
    };

    float acc[2][8][4];
#pragma unroll
    for (int i = 0; i < 2; i++)
#pragma unroll
        for (int j = 0; j < 8; j++)
#pragma unroll
            for (int c = 0; c < 4; c++) acc[i][j][c] = 0.f;

    // prologue: prefetch chunks 0 and 1
    copyAB(0, 0);
    copyAB(1, 1);

#pragma unroll 1
    for (int kc = 0; kc < 8; kc++) {
        if (kc < 6)
            asm volatile("cp.async.wait_group 1;" ::: "memory");
        else
            asm volatile("cp.async.wait_group 0;" ::: "memory");
        __syncthreads();

        if (kc < 6) copyAB(kc + 2, (kc + 2) % 3);

        const uint32_t* Ab = smem + (kc % 3) * 8192;
        const uint32_t* Bb = Ab + 4096;
#pragma unroll
        for (int s = 0; s < 4; s++) {
            uint32_t af[2][4];
            uint32_t bf[8][2];
#pragma unroll
            for (int mi = 0; mi < 2; mi++) {
                const uint4 va = *(const uint4*)
                    (Ab + (((warpM * 2 + mi) * 4 + s) * 32 + lane) * 4);
                af[mi][0] = va.x; af[mi][1] = va.y; af[mi][2] = va.z; af[mi][3] = va.w;
            }
#pragma unroll
            for (int p = 0; p < 4; p++) {
                const uint4 vb = *(const uint4*)
                    (Bb + (((warpN * 4 + p) * 4 + s) * 32 + lane) * 4);
                bf[2*p][0]   = vb.x; bf[2*p][1]   = vb.y;
                bf[2*p+1][0] = vb.z; bf[2*p+1][1] = vb.w;
            }
#pragma unroll
            for (int mi = 0; mi < 2; mi++)
#pragma unroll
                for (int j = 0; j < 8; j++)
                    HMMA16816(acc[mi][j], af[mi][0], af[mi][1], af[mi][2], af[mi][3],
                              bf[j][0], bf[j][1]);
        }
    }

    // epilogue: registers -> gmem, +bias, float2 stores
    const int cpair = (lane & 3) * 2;
    const int rsub  = lane >> 2;
#pragma unroll
    for (int j = 0; j < 8; j++) {
        const int col = v0 + warpN * 64 + j * 8 + cpair;
        if (col >= V_) continue;                  // V_ even: pair never straddles
        const float2 bb = *(const float2*)(bout + col);
#pragma unroll
        for (int mi = 0; mi < 2; mi++) {
            const long rr = r0 + warpM * 32 + mi * 16 + rsub;
            float2 o0, o1;
            o0.x = acc[mi][j][0] + bb.x;
            o0.y = acc[mi][j][1] + bb.y;
            o1.x = acc[mi][j][2] + bb.x;
            o1.y = acc[mi][j][3] + bb.y;
            *(float2*)(out + rr * (long)V_ + col)       = o0;
            *(float2*)(out + (rr + 8) * (long)V_ + col) = o1;
        }
    }
}

// ---------------------------------------------------------------------------
extern "C" void kernel_launch(void* const* d_in, const int* in_sizes, int n_in,
                              void* d_out, int out_size)
{
    (void)in_sizes; (void)n_in; (void)out_size;
    const float* encoder_out = (const float*)d_in[0];  // [8,200,512]
    const float* decoder_out = (const float*)d_in[1];  // [8,50,512]
    const float* W_enc       = (const float*)d_in[2];  // [512,512]
    const float* b_enc       = (const float*)d_in[3];  // [512]
    const float* W_dec       = (const float*)d_in[4];  // [512,512]
    const float* b_dec       = (const float*)d_in[5];  // [512]
    const float* W_out       = (const float*)d_in[6];  // [500,512]
    const float* b_out       = (const float*)d_in[7];  // [500]
    float* out = (float*)d_out;                        // [8,200,50,500]

    float* encP = nullptr;
    float* decP = nullptr;
    cudaGetSymbolAddress((void**)&encP, g_encP);
    cudaGetSymbolAddress((void**)&decP, g_decP);

    cudaFuncSetAttribute(joiner_hmma,
                         cudaFuncAttributeMaxDynamicSharedMemorySize, SMEM_BYTES);

    // pack W_out to paired fp16 fragment order
    pack_w<<<128, 256>>>(W_out);

    // projections via split-fp16 HMMA (enc: 25 mtiles, dec: 7 mtiles)
    {
        dim3 grid(8, 32);
        proj_hmma<<<grid, 256>>>(encoder_out, W_enc, b_enc, encP,
                                 decoder_out, W_dec, b_dec, decP);
    }
    // activations: tanh(encP+decP) -> fp16 fragment-packed gmem
    act_kernel<<<20000, 256>>>();

    // main pure fp16 GEMM (128x128 tiles, BK=64, 2 CTAs/SM)
    {
        dim3 grid(4, 625);   // N-tiles x M-tiles
        joiner_hmma<<<grid, 256, SMEM_BYTES>>>(b_out, out);
    }
}